// round 12
// baseline (speedup 1.0000x reference)
#include <cuda_runtime.h>
#include <cuda_bf16.h>

#define TOKENS 32768
#define DDIM 1024
#define RDIM 48
#define MTILE 256
#define THREADS 512
#define NCTAS (TOKENS / MTILE)   // 128 CTAs -> one wave
#define KC 32
#define NCH (DDIM / KC)          // 32 chunks per phase
#define NSTAGE 3

#define GWST 1032                // bf16 elems/row (2064B; mod128=16 -> LDSM conflict-free)
#define WUST 56                  // bf16 elems/row (112B;  mod128 distinct -> conflict-free)
#define XROW 36                  // fp32 elems/row (144B)
#define YS_STRIDE 52             // bf16
#define H2_STRIDE 52             // bf16

#define WBLK (16 * XROW * 4)     // 2304 B per warp per stage
#define XSTG (16 * WBLK)         // 36864 B per stage

// ---- smem layout (bytes) ----
#define OFF_W   0
#define SZ_W    (DDIM * WUST * 2)          // 114688 (gw uses 99072; spare below)
#define OFF_A48 99072                      // 9216   (in W spare, dead before wu staging)
#define OFF_C48 108288                     // 192
#define OFF_SUM 108480                     // 1024
#define OFF_SSQ 109504                     // 1024
#define OFF_SGW 110528                     // 192
#define OFF_CB  110720                     // 192  (ends 110912 <= 114688)
#define OFF_XST (OFF_W + SZ_W)             // 114688: 3 stages
#define OFF_Y   (OFF_XST + XSTG)           // y overlays stage 1
#define OFF_H2  (OFF_XST + 2 * XSTG)       // h2 overlays stage 2
#define SMEM_TOTAL (OFF_XST + NSTAGE * XSTG)   // 225280 <= 232448

__device__ __forceinline__ float gelu_exact(float v) {
    return 0.5f * v * (1.0f + erff(v * 0.70710678118654752440f));
}

__device__ __forceinline__ void mma_bf16(float* c, unsigned a0, unsigned a1, unsigned a2,
                                         unsigned a3, unsigned b0, unsigned b1) {
    asm volatile(
        "mma.sync.aligned.m16n8k16.row.col.f32.bf16.bf16.f32 "
        "{%0,%1,%2,%3}, {%4,%5,%6,%7}, {%8,%9}, {%0,%1,%2,%3};\n"
        : "+f"(c[0]), "+f"(c[1]), "+f"(c[2]), "+f"(c[3])
        : "r"(a0), "r"(a1), "r"(a2), "r"(a3), "r"(b0), "r"(b1));
}

__device__ __forceinline__ void ldsm_x4(unsigned* r, unsigned addr) {
    asm volatile("ldmatrix.sync.aligned.m8n8.x4.shared.b16 {%0,%1,%2,%3}, [%4];"
                 : "=r"(r[0]), "=r"(r[1]), "=r"(r[2]), "=r"(r[3]) : "r"(addr));
}

__device__ __forceinline__ unsigned pack2(float a, float b) {
    __nv_bfloat162 p = __floats2bfloat162_rn(a, b);
    return *(unsigned*)&p;
}
__device__ __forceinline__ uint2 pack_bf16x4(float a, float b, float c, float d) {
    uint2 pk;
    pk.x = pack2(a, b);
    pk.y = pack2(c, d);
    return pk;
}

__device__ __forceinline__ void cp16(unsigned dst, const void* src) {
    asm volatile("cp.async.cg.shared.global [%0], [%1], 16;\n" :: "r"(dst), "l"(src));
}
__device__ __forceinline__ void cp_commit() {
    asm volatile("cp.async.commit_group;\n");
}
template <int N>
__device__ __forceinline__ void cp_wait() {
    asm volatile("cp.async.wait_group %0;\n" :: "n"(N));
}

// ============================================================================
// Single fused kernel. Resident weights (per-CTA staged) + per-warp private
// KC=32 x pipelines (full 128B-row coalescing, zero mainloop CTA barriers).
// ============================================================================
__global__ void __launch_bounds__(THREADS, 1) fused_kernel(
    const float* __restrict__ x, const float* __restrict__ gamma,
    const float* __restrict__ beta, const float* __restrict__ w_down,
    const float* __restrict__ w_to_mv, const float* __restrict__ w_equi,
    const float* __restrict__ b_equi, const float* __restrict__ w_from_mv,
    const float* __restrict__ w_up, const float* __restrict__ scale_p,
    float* __restrict__ out)
{
    extern __shared__ char smem[];
    const unsigned sbase = (unsigned)__cvta_generic_to_shared(smem);
    __nv_bfloat16* y_s  = (__nv_bfloat16*)(smem + OFF_Y);
    __nv_bfloat16* h2_s = (__nv_bfloat16*)(smem + OFF_H2);
    float* sum_s   = (float*)(smem + OFF_SUM);
    float* sumsq_s = (float*)(smem + OFF_SSQ);
    float* sumgw_s = (float*)(smem + OFF_SGW);
    float* cb_s    = (float*)(smem + OFF_CB);
    float* c48_s   = (float*)(smem + OFF_C48);
    float* A48T_s  = (float*)(smem + OFF_A48);

    const int tid = threadIdx.x, lane = tid & 31, warp = tid >> 5;
    const int g = lane >> 2, t4 = lane & 3;
    const int tok0 = blockIdx.x * MTILE;
    const int mrow = warp * 16;

    // LDSM lane mapping
    const int bn = ((lane >> 4) << 3) + (lane & 7);
    const int kh = (lane >> 3) & 1;

    // per-warp cp mapping: p=0..3, row=p*4+(lane>>3), 8 lanes x 16B = 128B/row
    const int lr = lane >> 3, lc16 = (lane & 7) * 16, lc4 = (lane & 7) * 4;
    const unsigned mystage = sbase + OFF_XST + warp * WBLK;
    const float* xwarp = x + (size_t)(tok0 + mrow) * DDIM;

    // ---- issue phase-A chunks 0,1 (per-warp private pipelines) ----
    #pragma unroll
    for (int kn = 0; kn < 2; kn++) {
        unsigned d = mystage + kn * XSTG;
        const float* s = xwarp + kn * KC;
        #pragma unroll
        for (int p = 0; p < 4; p++) {
            int row = p * 4 + lr;
            cp16(d + row * 144 + lc16, s + (size_t)row * DDIM + lc4);
        }
        cp_commit();
    }

    // ---- stage gw = bf16(gamma (*) w_down) resident (L2-broadcast hot) ----
    {
        const float4* wd4 = (const float4*)w_down;
        const float4* g4  = (const float4*)gamma;
        for (int i = tid; i < RDIM * (DDIM / 4); i += THREADS) {
            int r = i >> 8, c4 = i & 255;
            float4 w = wd4[i];
            float4 gv = g4[c4];
            *(uint2*)(smem + OFF_W + r * (GWST * 2) + c4 * 8) =
                pack_bf16x4(w.x * gv.x, w.y * gv.y, w.z * gv.z, w.w * gv.w);
        }
    }
    __syncthreads();   // gw visible to all (ldsm + sumgw)

    // ---- per-CTA prep into W spare: sumgw/cb, c48, A48T ----
    #pragma unroll 1
    for (int rr = 0; rr < 3; rr++) {
        int r = warp + rr * 16;
        float sg = 0.f, scb = 0.f;
        #pragma unroll
        for (int it = 0; it < 8; it++) {
            int d = it * 128 + lane * 4;
            uint2 pk = *(const uint2*)(smem + OFF_W + r * (GWST * 2) + d * 2);
            __nv_bfloat162 b0 = *(__nv_bfloat162*)&pk.x;
            __nv_bfloat162 b1 = *(__nv_bfloat162*)&pk.y;
            sg += __bfloat162float(b0.x) + __bfloat162float(b0.y)
                + __bfloat162float(b1.x) + __bfloat162float(b1.y);
            float4 wv = *(const float4*)(w_down + (size_t)r * DDIM + d);
            float4 bv = *(const float4*)(beta + d);
            scb += wv.x * bv.x + wv.y * bv.y + wv.z * bv.z + wv.w * bv.w;
        }
        #pragma unroll
        for (int off = 16; off; off >>= 1) {
            sg  += __shfl_xor_sync(0xffffffffu, sg, off);
            scb += __shfl_xor_sync(0xffffffffu, scb, off);
        }
        if (lane == 0) { sumgw_s[r] = sg; cb_s[r] = scb; }
    }
    for (int i = tid; i < RDIM; i += THREADS)
        c48_s[i] = __ldg(w_from_mv + i * 16) * __ldg(b_equi);
    for (int i = tid; i < RDIM * RDIM; i += THREADS) {
        int rp = i / RDIM, r = i - rp * RDIM;
        float a = 0.f;
        #pragma unroll
        for (int m = 0; m < 16; m++) {
            int gidx = (m == 0) ? 0 : (m < 5) ? 1 : (m < 11) ? 2 : (m < 15) ? 3 : 4;
            a += __ldg(w_from_mv + r * 16 + m) * __ldg(w_equi + gidx)
               * __ldg(w_to_mv + m * RDIM + rp);
        }
        A48T_s[i] = a;
    }

    // ---- phase A mainloop: per-warp, barrier-free, KC=32 ----
    float acc[6][4];
    #pragma unroll
    for (int j = 0; j < 6; j++)
        #pragma unroll
        for (int q = 0; q < 4; q++) acc[j][q] = 0.f;
    float ps0 = 0.f, pss0 = 0.f, ps1 = 0.f, pss1 = 0.f;

    #pragma unroll 2
    for (int kc = 0; kc < NCH; kc++) {
        int kn = kc + 2;
        if (kn < NCH) {
            unsigned d = mystage + (kn % NSTAGE) * XSTG;
            const float* s = xwarp + kn * KC;
            #pragma unroll
            for (int p = 0; p < 4; p++) {
                int row = p * 4 + lr;
                cp16(d + row * 144 + lc16, s + (size_t)row * DDIM + lc4);
            }
        }
        cp_commit();
        cp_wait<2>();
        __syncwarp();

        const float* xs = (const float*)(smem + OFF_XST + (kc % NSTAGE) * XSTG + warp * WBLK);
        #pragma unroll
        for (int kk = 0; kk < 2; kk++) {
            int cb_ = kk * 16;
            float2 p00 = *(const float2*)(xs + g * XROW + cb_ + t4 * 2);
            float2 p10 = *(const float2*)(xs + (g + 8) * XROW + cb_ + t4 * 2);
            float2 p01 = *(const float2*)(xs + g * XROW + cb_ + 8 + t4 * 2);
            float2 p11 = *(const float2*)(xs + (g + 8) * XROW + cb_ + 8 + t4 * 2);
            ps0  += (p00.x + p00.y) + (p01.x + p01.y);
            pss0 += (p00.x * p00.x + p00.y * p00.y) + (p01.x * p01.x + p01.y * p01.y);
            ps1  += (p10.x + p10.y) + (p11.x + p11.y);
            pss1 += (p10.x * p10.x + p10.y * p10.y) + (p11.x * p11.x + p11.y * p11.y);
            unsigned a0 = pack2(p00.x, p00.y);
            unsigned a1 = pack2(p10.x, p10.y);
            unsigned a2 = pack2(p01.x, p01.y);
            unsigned a3 = pack2(p11.x, p11.y);

            unsigned wb = sbase + OFF_W + bn * (GWST * 2) + kh * 16 + kc * 64 + kk * 32;
            unsigned br[3][4];
            #pragma unroll
            for (int p = 0; p < 3; p++)
                ldsm_x4(br[p], wb + p * 16 * (GWST * 2));
            #pragma unroll
            for (int j = 0; j < 6; j++)
                mma_bf16(acc[j], a0, a1, a2, a3,
                         br[j >> 1][(j & 1) * 2], br[j >> 1][(j & 1) * 2 + 1]);
        }
    }

    // ---- stats reduce; prefetch C chunk 0 into stage 0 (warp block is free) ----
    #pragma unroll
    for (int off = 1; off <= 2; off <<= 1) {
        ps0  += __shfl_xor_sync(0xffffffffu, ps0, off);
        pss0 += __shfl_xor_sync(0xffffffffu, pss0, off);
        ps1  += __shfl_xor_sync(0xffffffffu, ps1, off);
        pss1 += __shfl_xor_sync(0xffffffffu, pss1, off);
    }
    if (t4 == 0) {
        sum_s[mrow + g] = ps0;     sumsq_s[mrow + g] = pss0;
        sum_s[mrow + g + 8] = ps1; sumsq_s[mrow + g + 8] = pss1;
    }
    {
        unsigned d = mystage;   // stage 0
        #pragma unroll
        for (int p = 0; p < 4; p++) {
            int row = p * 4 + lr;
            cp16(d + row * 144 + lc16, xwarp + (size_t)row * DDIM + lc4);
        }
        cp_commit();            // group 1 of phase-C pipeline
    }
    __syncthreads();
    if (tid < MTILE) {
        float mu  = sum_s[tid] * (1.0f / DDIM);
        float var = sumsq_s[tid] * (1.0f / DDIM) - mu * mu;
        sum_s[tid]   = mu;
        sumsq_s[tid] = rsqrtf(var + 1e-5f);
    }
    __syncthreads();

    // ---- y = gelu(rinv*(acc - mu*sumgw) + cb) -> bf16 (stage-1 overlay) ----
    {
        int r0 = mrow + g, r1 = r0 + 8;
        float mu0 = sum_s[r0], ri0 = sumsq_s[r0];
        float mu1 = sum_s[r1], ri1 = sumsq_s[r1];
        #pragma unroll
        for (int j = 0; j < 6; j++) {
            int c0 = j * 8 + t4 * 2, c1 = c0 + 1;
            float y00 = gelu_exact(ri0 * (acc[j][0] - mu0 * sumgw_s[c0]) + cb_s[c0]);
            float y01 = gelu_exact(ri0 * (acc[j][1] - mu0 * sumgw_s[c1]) + cb_s[c1]);
            float y10 = gelu_exact(ri1 * (acc[j][2] - mu1 * sumgw_s[c0]) + cb_s[c0]);
            float y11 = gelu_exact(ri1 * (acc[j][3] - mu1 * sumgw_s[c1]) + cb_s[c1]);
            *(__nv_bfloat162*)(y_s + r0 * YS_STRIDE + c0) = __floats2bfloat162_rn(y00, y01);
            *(__nv_bfloat162*)(y_s + r1 * YS_STRIDE + c0) = __floats2bfloat162_rn(y10, y11);
        }
    }
    __syncthreads();

    // ---- middle: h2 = gelu(A48 @ y + c48) -> bf16 (stage-2 overlay) ----
    {
        int t = tid >> 1;
        int rbase = (tid & 1) * 24;
        const __nv_bfloat16* yrow = y_s + t * YS_STRIDE;
        float h2v[24];
        #pragma unroll
        for (int r = 0; r < 24; r++) h2v[r] = c48_s[rbase + r];
        #pragma unroll 4
        for (int kp2 = 0; kp2 < RDIM / 2; kp2++) {
            __nv_bfloat162 yp = *(const __nv_bfloat162*)(yrow + kp2 * 2);
            float yv0 = __bfloat162float(yp.x), yv1 = __bfloat162float(yp.y);
            const float* a0 = A48T_s + (kp2 * 2) * RDIM + rbase;
            const float* a1 = a0 + RDIM;
            #pragma unroll
            for (int r = 0; r < 24; r++) h2v[r] += yv0 * a0[r] + yv1 * a1[r];
        }
        __nv_bfloat16* op = h2_s + t * H2_STRIDE + rbase;
        #pragma unroll
        for (int r = 0; r < 24; r += 2) {
            __nv_bfloat162 p = __floats2bfloat162_rn(gelu_exact(h2v[r]), gelu_exact(h2v[r + 1]));
            *(__nv_bfloat162*)(op + r) = p;
        }
    }
    __syncthreads();   // h2 complete; spare arrays (A48T/c48/sum/..) now dead

    // ---- stage wu = bf16(w_up) resident (overwrites gw + spare) ----
    {
        const float4* wu4 = (const float4*)w_up;
        for (int i = tid; i < DDIM * (RDIM / 4); i += THREADS) {
            int d = i / 12, q = i - d * 12;
            float4 v = wu4[i];
            *(uint2*)(smem + OFF_W + d * (WUST * 2) + q * 8) =
                pack_bf16x4(v.x, v.y, v.z, v.w);
        }
    }
    __syncthreads();

    // ---- afr from h2, then free stage 2 for the C pipeline ----
    unsigned afr[3][4];
    #pragma unroll
    for (int kk = 0; kk < 3; kk++) {
        afr[kk][0] = *(const unsigned*)(h2_s + (mrow + g) * H2_STRIDE + kk * 16 + t4 * 2);
        afr[kk][1] = *(const unsigned*)(h2_s + (mrow + g + 8) * H2_STRIDE + kk * 16 + t4 * 2);
        afr[kk][2] = *(const unsigned*)(h2_s + (mrow + g) * H2_STRIDE + kk * 16 + 8 + t4 * 2);
        afr[kk][3] = *(const unsigned*)(h2_s + (mrow + g + 8) * H2_STRIDE + kk * 16 + 8 + t4 * 2);
    }
    float scale = __ldg(scale_p);
    __syncthreads();   // all warps got afr; stages 1,2 free for cp

    {   // C chunk 1 -> stage 1
        unsigned d = mystage + 1 * XSTG;
        const float* s = xwarp + 1 * KC;
        #pragma unroll
        for (int p = 0; p < 4; p++) {
            int row = p * 4 + lr;
            cp16(d + row * 144 + lc16, s + (size_t)row * DDIM + lc4);
        }
        cp_commit();
    }

    // ---- phase C mainloop: per-warp, barrier-free ----
    #pragma unroll 2
    for (int nc = 0; nc < NCH; nc++) {
        int nn = nc + 2;
        if (nn < NCH) {
            unsigned d = mystage + (nn % NSTAGE) * XSTG;
            const float* s = xwarp + nn * KC;
            #pragma unroll
            for (int p = 0; p < 4; p++) {
                int row = p * 4 + lr;
                cp16(d + row * 144 + lc16, s + (size_t)row * DDIM + lc4);
            }
        }
        cp_commit();
        cp_wait<2>();
        __syncwarp();

        const float* xs = (const float*)(smem + OFF_XST + (nc % NSTAGE) * XSTG + warp * WBLK);
        unsigned wub = sbase + OFF_W + (nc * 32 + bn) * (WUST * 2) + kh * 16;

        float uacc[4][4];
        #pragma unroll
        for (int j = 0; j < 4; j++)
            #pragma unroll
            for (int q = 0; q < 4; q++) uacc[j][q] = 0.f;

        #pragma unroll
        for (int kk = 0; kk < 3; kk++) {
            unsigned br[2][4];
            ldsm_x4(br[0], wub + kk * 32);
            ldsm_x4(br[1], wub + 16 * (WUST * 2) + kk * 32);
            #pragma unroll
            for (int j = 0; j < 4; j++)
                mma_bf16(uacc[j], afr[kk][0], afr[kk][1], afr[kk][2], afr[kk][3],
                         br[j >> 1][(j & 1) * 2], br[j >> 1][(j & 1) * 2 + 1]);
        }
        size_t row0 = (size_t)(tok0 + mrow + g) * DDIM + nc * KC;
        size_t row1 = row0 + 8 * (size_t)DDIM;
        #pragma unroll
        for (int j = 0; j < 4; j++) {
            int lc = j * 8 + t4 * 2;
            float2 xv0 = *(const float2*)(xs + g * XROW + lc);
            float2 xv1 = *(const float2*)(xs + (g + 8) * XROW + lc);
            float2 o0 = make_float2(xv0.x + scale * uacc[j][0], xv0.y + scale * uacc[j][1]);
            float2 o1 = make_float2(xv1.x + scale * uacc[j][2], xv1.y + scale * uacc[j][3]);
            __stcs((float2*)(out + row0 + lc), o0);
            __stcs((float2*)(out + row1 + lc), o1);
        }
    }
}

extern "C" void kernel_launch(void* const* d_in, const int* in_sizes, int n_in,
                              void* d_out, int out_size) {
    const float* x         = (const float*)d_in[0];
    const float* gamma     = (const float*)d_in[1];
    const float* beta      = (const float*)d_in[2];
    const float* w_down    = (const float*)d_in[3];
    const float* w_to_mv   = (const float*)d_in[4];
    const float* w_equi    = (const float*)d_in[5];
    const float* b_equi    = (const float*)d_in[6];
    const float* w_from_mv = (const float*)d_in[7];
    const float* w_up      = (const float*)d_in[8];
    const float* scale     = (const float*)d_in[9];
    float* out = (float*)d_out;

    cudaFuncSetAttribute(fused_kernel, cudaFuncAttributeMaxDynamicSharedMemorySize, SMEM_TOTAL);
    fused_kernel<<<NCTAS, THREADS, SMEM_TOTAL>>>(x, gamma, beta, w_down, w_to_mv, w_equi,
                                                 b_equi, w_from_mv, w_up, scale, out);
}

// round 13
// speedup vs baseline: 1.0165x; 1.0165x over previous
#include <cuda_runtime.h>
#include <cuda_bf16.h>

#define TOKENS 32768
#define DDIM 1024
#define RDIM 48
#define MTILE 256
#define THREADS 512
#define NCTAS (TOKENS / MTILE)   // 128 CTAs -> one wave
#define KC 32
#define NCH (DDIM / KC)          // 32 chunks per phase

#define GWST 1032                // bf16 elems/row (2064B; 8-row ldsm conflict-free)
#define WUST 56                  // bf16 elems/row (112B; 8-row ldsm conflict-free)
#define YS_STRIDE 52             // bf16
#define H2_STRIDE 52             // bf16

// ---- smem layout (bytes): NO x staging at all ----
#define OFF_W   0
#define SZ_W    (DDIM * WUST * 2)                 // 114688 (gw uses 48*2064=99072)
#define OFF_Y   (OFF_W + SZ_W)                    // 26624
#define OFF_H2  (OFF_Y + MTILE * YS_STRIDE * 2)   // 26624
#define OFF_A48 (OFF_H2 + MTILE * H2_STRIDE * 2)  // 9216
#define OFF_SGW (OFF_A48 + RDIM * RDIM * 4)       // 192
#define OFF_CB  (OFF_SGW + RDIM * 4)              // 192
#define OFF_C48 (OFF_CB + RDIM * 4)               // 192
#define SMEM_TOTAL (OFF_C48 + RDIM * 4)           // 177728

// ---- global scratch (prep output) ----
__device__ __align__(16) __nv_bfloat16 g_gw[RDIM * DDIM];   // gamma (*) w_down
__device__ __align__(16) __nv_bfloat16 g_wu[DDIM * RDIM];
__device__ float g_sumgw[RDIM];
__device__ float g_cb[RDIM];
__device__ float g_c48[RDIM];
__device__ float g_A48T[RDIM * RDIM];

__device__ __forceinline__ float gelu_exact(float v) {
    return 0.5f * v * (1.0f + erff(v * 0.70710678118654752440f));
}

__device__ __forceinline__ void mma_bf16(float* c, unsigned a0, unsigned a1, unsigned a2,
                                         unsigned a3, unsigned b0, unsigned b1) {
    asm volatile(
        "mma.sync.aligned.m16n8k16.row.col.f32.bf16.bf16.f32 "
        "{%0,%1,%2,%3}, {%4,%5,%6,%7}, {%8,%9}, {%0,%1,%2,%3};\n"
        : "+f"(c[0]), "+f"(c[1]), "+f"(c[2]), "+f"(c[3])
        : "r"(a0), "r"(a1), "r"(a2), "r"(a3), "r"(b0), "r"(b1));
}

__device__ __forceinline__ void ldsm_x4(unsigned* r, unsigned addr) {
    asm volatile("ldmatrix.sync.aligned.m8n8.x4.shared.b16 {%0,%1,%2,%3}, [%4];"
                 : "=r"(r[0]), "=r"(r[1]), "=r"(r[2]), "=r"(r[3]) : "r"(addr));
}

__device__ __forceinline__ unsigned pack2(float a, float b) {
    __nv_bfloat162 p = __floats2bfloat162_rn(a, b);
    return *(unsigned*)&p;
}
__device__ __forceinline__ uint2 pack_bf16x4(float a, float b, float c, float d) {
    uint2 pk;
    pk.x = pack2(a, b);
    pk.y = pack2(c, d);
    return pk;
}

__device__ __forceinline__ void cp16(unsigned dst, const void* src) {
    asm volatile("cp.async.cg.shared.global [%0], [%1], 16;\n" :: "r"(dst), "l"(src));
}
__device__ __forceinline__ void cp_commit() {
    asm volatile("cp.async.commit_group;\n");
}
template <int N>
__device__ __forceinline__ void cp_wait() {
    asm volatile("cp.async.wait_group %0;\n" :: "n"(N));
}

// Direct-LDG chunk loader in mma A-frag layout: 8 float2 per chunk per lane.
// d[2i]  = (row g,   col base + i*8 + t2),  d[2i+1] = (row g+8, same col)
__device__ __forceinline__ void load_chunk(float2* d, const float* base, int g, int t2) {
    #pragma unroll
    for (int i = 0; i < 4; i++) {
        d[2 * i]     = *(const float2*)(base + (size_t)g * DDIM + i * 8 + t2);
        d[2 * i + 1] = *(const float2*)(base + (size_t)(g + 8) * DDIM + i * 8 + t2);
    }
}

// ============================================================================
// prep: gamma-folded w_down -> bf16, w_up -> bf16, sumgw/cb, collapsed 48x48.
// ============================================================================
__global__ void prep_kernel(const float* __restrict__ gamma, const float* __restrict__ beta,
                            const float* __restrict__ w_down, const float* __restrict__ w_to_mv,
                            const float* __restrict__ w_equi, const float* __restrict__ b_equi,
                            const float* __restrict__ w_from_mv, const float* __restrict__ w_up) {
    int tid = threadIdx.x, lane = tid & 31;
    int gtid = blockIdx.x * blockDim.x + tid;
    int nth = gridDim.x * blockDim.x;
    int gwarp = gtid >> 5;

    if (gwarp < RDIM) {
        int r = gwarp;
        float s = 0.f, cb = 0.f;
        #pragma unroll
        for (int it = 0; it < 8; it++) {
            int d = it * 128 + lane * 4;
            float4 w  = *(const float4*)(w_down + (size_t)r * DDIM + d);
            float4 gv = *(const float4*)(gamma + d);
            float4 bv = *(const float4*)(beta + d);
            uint2 pk = pack_bf16x4(w.x * gv.x, w.y * gv.y, w.z * gv.z, w.w * gv.w);
            *(uint2*)(g_gw + (size_t)r * DDIM + d) = pk;
            __nv_bfloat162 b0 = *(__nv_bfloat162*)&pk.x;
            __nv_bfloat162 b1 = *(__nv_bfloat162*)&pk.y;
            s += __bfloat162float(b0.x) + __bfloat162float(b0.y)
               + __bfloat162float(b1.x) + __bfloat162float(b1.y);
            cb += w.x * bv.x + w.y * bv.y + w.z * bv.z + w.w * bv.w;
        }
        #pragma unroll
        for (int off = 16; off; off >>= 1) {
            s  += __shfl_xor_sync(0xffffffffu, s, off);
            cb += __shfl_xor_sync(0xffffffffu, cb, off);
        }
        if (lane == 0) { g_sumgw[r] = s; g_cb[r] = cb; }
    }
    for (int i = gtid; i < DDIM * RDIM / 4; i += nth) {
        float4 v = ((const float4*)w_up)[i];
        ((uint2*)g_wu)[i] = pack_bf16x4(v.x, v.y, v.z, v.w);
    }
    for (int i = gtid; i < RDIM * RDIM; i += nth) {
        int rp = i / RDIM, r = i - rp * RDIM;
        float a = 0.f;
        #pragma unroll
        for (int m = 0; m < 16; m++) {
            int gidx = (m == 0) ? 0 : (m < 5) ? 1 : (m < 11) ? 2 : (m < 15) ? 3 : 4;
            a += __ldg(w_from_mv + r * 16 + m) * __ldg(w_equi + gidx)
               * __ldg(w_to_mv + m * RDIM + rp);
        }
        g_A48T[i] = a;
    }
    for (int i = gtid; i < RDIM; i += nth)
        g_c48[i] = __ldg(w_from_mv + i * 16) * __ldg(b_equi);
}

// ============================================================================
// Fused kernel: x via direct LDG into fragments (no smem staging, no mainloop
// barriers). Weights resident in smem via one cp.async burst per phase.
// ============================================================================
__global__ void __launch_bounds__(THREADS, 1) fused_kernel(
    const float* __restrict__ x, const float* __restrict__ scale_p,
    float* __restrict__ out)
{
    extern __shared__ char smem[];
    const unsigned sbase = (unsigned)__cvta_generic_to_shared(smem);
    __nv_bfloat16* y_s  = (__nv_bfloat16*)(smem + OFF_Y);
    __nv_bfloat16* h2_s = (__nv_bfloat16*)(smem + OFF_H2);
    float* A48T_s  = (float*)(smem + OFF_A48);
    float* sumgw_s = (float*)(smem + OFF_SGW);
    float* cb_s    = (float*)(smem + OFF_CB);
    float* c48_s   = (float*)(smem + OFF_C48);

    const int tid = threadIdx.x, lane = tid & 31, warp = tid >> 5;
    const int g = lane >> 2, t4 = lane & 3, t2 = t4 * 2;
    const int tok0 = blockIdx.x * MTILE;
    const int mrow = warp * 16;

    // LDSM lane mapping
    const int bn = ((lane >> 4) << 3) + (lane & 7);
    const int kh = (lane >> 3) & 1;

    const float* xwarp = x + (size_t)(tok0 + mrow) * DDIM;

    // ---- issue resident-gw cp.async burst (48 rows x 2048B -> 2064B stride) ----
    for (int i = tid; i < RDIM * 128; i += THREADS) {
        int r = i >> 7, s = i & 127;
        cp16(sbase + OFF_W + r * (GWST * 2) + s * 16,
             (const char*)g_gw + (size_t)r * 2048 + s * 16);
    }
    cp_commit();

    // ---- preload x chunks 0,1 directly into fragment registers ----
    float2 st[2][8];
    load_chunk(st[0], xwarp, g, t2);
    load_chunk(st[1], xwarp + KC, g, t2);

    // ---- small precomputed arrays ----
    for (int i = tid; i < RDIM * RDIM; i += THREADS) A48T_s[i] = g_A48T[i];
    for (int i = tid; i < RDIM; i += THREADS) {
        sumgw_s[i] = g_sumgw[i]; cb_s[i] = g_cb[i]; c48_s[i] = g_c48[i];
    }
    float scale = __ldg(scale_p);

    cp_wait<0>();
    __syncthreads();   // gw resident + arrays visible

    // ---- phase A mainloop: per-warp, zero barriers, direct LDG ----
    float acc[6][4];
    #pragma unroll
    for (int j = 0; j < 6; j++)
        #pragma unroll
        for (int q = 0; q < 4; q++) acc[j][q] = 0.f;
    float ps0 = 0.f, pss0 = 0.f, ps1 = 0.f, pss1 = 0.f;

    const unsigned gwb = sbase + OFF_W + bn * (GWST * 2) + kh * 16;

    #pragma unroll 2
    for (int kc = 0; kc < NCH; kc++) {
        float2 v[8];
        #pragma unroll
        for (int i = 0; i < 8; i++) v[i] = st[kc & 1][i];
        if (kc + 2 < NCH)   // overwrite the freed buffer ASAP -> distance-2 prefetch
            load_chunk(st[kc & 1], xwarp + (kc + 2) * KC, g, t2);

        #pragma unroll
        for (int kk = 0; kk < 2; kk++) {
            float2 p00 = v[kk * 4 + 0], p10 = v[kk * 4 + 1];
            float2 p01 = v[kk * 4 + 2], p11 = v[kk * 4 + 3];
            ps0  += (p00.x + p00.y) + (p01.x + p01.y);
            pss0 += (p00.x * p00.x + p00.y * p00.y) + (p01.x * p01.x + p01.y * p01.y);
            ps1  += (p10.x + p10.y) + (p11.x + p11.y);
            pss1 += (p10.x * p10.x + p10.y * p10.y) + (p11.x * p11.x + p11.y * p11.y);
            unsigned a0 = pack2(p00.x, p00.y);
            unsigned a1 = pack2(p10.x, p10.y);
            unsigned a2 = pack2(p01.x, p01.y);
            unsigned a3 = pack2(p11.x, p11.y);

            unsigned br[3][4];
            #pragma unroll
            for (int p = 0; p < 3; p++)
                ldsm_x4(br[p], gwb + p * 16 * (GWST * 2) + kc * 64 + kk * 32);
            #pragma unroll
            for (int j = 0; j < 6; j++)
                mma_bf16(acc[j], a0, a1, a2, a3,
                         br[j >> 1][(j & 1) * 2], br[j >> 1][(j & 1) * 2 + 1]);
        }
    }

    // ---- stats: reduce over the 4 t4-lanes; LN params stay in registers ----
    #pragma unroll
    for (int off = 1; off <= 2; off <<= 1) {
        ps0  += __shfl_xor_sync(0xffffffffu, ps0, off);
        pss0 += __shfl_xor_sync(0xffffffffu, pss0, off);
        ps1  += __shfl_xor_sync(0xffffffffu, ps1, off);
        pss1 += __shfl_xor_sync(0xffffffffu, pss1, off);
    }
    float mu0 = ps0 * (1.0f / DDIM);
    float ri0 = rsqrtf(pss0 * (1.0f / DDIM) - mu0 * mu0 + 1e-5f);
    float mu1 = ps1 * (1.0f / DDIM);
    float ri1 = rsqrtf(pss1 * (1.0f / DDIM) - mu1 * mu1 + 1e-5f);

    __syncthreads();   // all gw reads done -> safe to overwrite W region

    // ---- issue resident-wu cp.async burst (overlaps the whole mid-section) ----
    for (int i = tid; i < DDIM * 6; i += THREADS) {
        int d = i / 6, s = i - d * 6;
        cp16(sbase + OFF_W + d * (WUST * 2) + s * 16,
             (const char*)g_wu + (size_t)d * 96 + s * 16);
    }
    cp_commit();

    // ---- y = gelu(rinv*(acc - mu*sumgw) + cb) -> bf16 ----
    {
        int r0 = mrow + g, r1 = r0 + 8;
        #pragma unroll
        for (int j = 0; j < 6; j++) {
            int c0 = j * 8 + t2, c1 = c0 + 1;
            float y00 = gelu_exact(ri0 * (acc[j][0] - mu0 * sumgw_s[c0]) + cb_s[c0]);
            float y01 = gelu_exact(ri0 * (acc[j][1] - mu0 * sumgw_s[c1]) + cb_s[c1]);
            float y10 = gelu_exact(ri1 * (acc[j][2] - mu1 * sumgw_s[c0]) + cb_s[c0]);
            float y11 = gelu_exact(ri1 * (acc[j][3] - mu1 * sumgw_s[c1]) + cb_s[c1]);
            *(__nv_bfloat162*)(y_s + r0 * YS_STRIDE + c0) = __floats2bfloat162_rn(y00, y01);
            *(__nv_bfloat162*)(y_s + r1 * YS_STRIDE + c0) = __floats2bfloat162_rn(y10, y11);
        }
    }

    // ---- prefetch phase-C x chunks 0,1 (residual) -> covered by middle ----
    load_chunk(st[0], xwarp, g, t2);
    load_chunk(st[1], xwarp + KC, g, t2);

    __syncthreads();   // y visible

    // ---- middle: h2 = gelu(A48 @ y + c48) -> bf16 ----
    {
        int t = tid >> 1;
        int rbase = (tid & 1) * 24;
        const __nv_bfloat16* yrow = y_s + t * YS_STRIDE;
        float h2v[24];
        #pragma unroll
        for (int r = 0; r < 24; r++) h2v[r] = c48_s[rbase + r];
        #pragma unroll 4
        for (int kp2 = 0; kp2 < RDIM / 2; kp2++) {
            __nv_bfloat162 yp = *(const __nv_bfloat162*)(yrow + kp2 * 2);
            float yv0 = __bfloat162float(yp.x), yv1 = __bfloat162float(yp.y);
            const float* a0 = A48T_s + (kp2 * 2) * RDIM + rbase;
            const float* a1 = a0 + RDIM;
            #pragma unroll
            for (int r = 0; r < 24; r++) h2v[r] += yv0 * a0[r] + yv1 * a1[r];
        }
        __nv_bfloat16* op = h2_s + t * H2_STRIDE + rbase;
        #pragma unroll
        for (int r = 0; r < 24; r += 2) {
            __nv_bfloat162 p = __floats2bfloat162_rn(gelu_exact(h2v[r]), gelu_exact(h2v[r + 1]));
            *(__nv_bfloat162*)(op + r) = p;
        }
    }
    cp_wait<0>();      // wu landed (own group)
    __syncthreads();   // h2 + wu visible to all

    // ---- phase C: out = x + scale*(h2 @ wu^T); per-warp, zero barriers ----
    unsigned afr[3][4];
    #pragma unroll
    for (int kk = 0; kk < 3; kk++) {
        afr[kk][0] = *(const unsigned*)(h2_s + (mrow + g) * H2_STRIDE + kk * 16 + t2);
        afr[kk][1] = *(const unsigned*)(h2_s + (mrow + g + 8) * H2_STRIDE + kk * 16 + t2);
        afr[kk][2] = *(const unsigned*)(h2_s + (mrow + g) * H2_STRIDE + kk * 16 + 8 + t2);
        afr[kk][3] = *(const unsigned*)(h2_s + (mrow + g + 8) * H2_STRIDE + kk * 16 + 8 + t2);
    }

    #pragma unroll 2
    for (int nc = 0; nc < NCH; nc++) {
        float2 xv[8];
        #pragma unroll
        for (int i = 0; i < 8; i++) xv[i] = st[nc & 1][i];
        if (nc + 2 < NCH)
            load_chunk(st[nc & 1], xwarp + (nc + 2) * KC, g, t2);

        unsigned wub = sbase + OFF_W + (nc * 32 + bn) * (WUST * 2) + kh * 16;
        float uacc[4][4];
        #pragma unroll
        for (int j = 0; j < 4; j++)
            #pragma unroll
            for (int q = 0; q < 4; q++) uacc[j][q] = 0.f;

        #pragma unroll
        for (int kk = 0; kk < 3; kk++) {
            unsigned br[2][4];
            ldsm_x4(br[0], wub + kk * 32);
            ldsm_x4(br[1], wub + 16 * (WUST * 2) + kk * 32);
            #pragma unroll
            for (int j = 0; j < 4; j++)
                mma_bf16(uacc[j], afr[kk][0], afr[kk][1], afr[kk][2], afr[kk][3],
                         br[j >> 1][(j & 1) * 2], br[j >> 1][(j & 1) * 2 + 1]);
        }
        size_t row0 = (size_t)(tok0 + mrow + g) * DDIM + nc * KC;
        size_t row1 = row0 + 8 * (size_t)DDIM;
        #pragma unroll
        for (int j = 0; j < 4; j++) {
            int lc = j * 8 + t2;
            float2 x0 = xv[2 * j], x1 = xv[2 * j + 1];
            float2 o0 = make_float2(x0.x + scale * uacc[j][0], x0.y + scale * uacc[j][1]);
            float2 o1 = make_float2(x1.x + scale * uacc[j][2], x1.y + scale * uacc[j][3]);
            __stcs((float2*)(out + row0 + lc), o0);
            __stcs((float2*)(out + row1 + lc), o1);
        }
    }
}

extern "C" void kernel_launch(void* const* d_in, const int* in_sizes, int n_in,
                              void* d_out, int out_size) {
    const float* x         = (const float*)d_in[0];
    const float* gamma     = (const float*)d_in[1];
    const float* beta      = (const float*)d_in[2];
    const float* w_down    = (const float*)d_in[3];
    const float* w_to_mv   = (const float*)d_in[4];
    const float* w_equi    = (const float*)d_in[5];
    const float* b_equi    = (const float*)d_in[6];
    const float* w_from_mv = (const float*)d_in[7];
    const float* w_up      = (const float*)d_in[8];
    const float* scale     = (const float*)d_in[9];
    float* out = (float*)d_out;

    cudaFuncSetAttribute(fused_kernel, cudaFuncAttributeMaxDynamicSharedMemorySize, SMEM_TOTAL);
    prep_kernel<<<128, 256>>>(gamma, beta, w_down, w_to_mv, w_equi, b_equi, w_from_mv, w_up);
    fused_kernel<<<NCTAS, THREADS, SMEM_TOTAL>>>(x, scale, out);
}

// round 14
// speedup vs baseline: 1.0547x; 1.0376x over previous
#include <cuda_runtime.h>
#include <cuda_bf16.h>

#define TOKENS 32768
#define DDIM 1024
#define RDIM 48
#define MTILE 256
#define THREADS 512
#define NCTAS (TOKENS / MTILE)   // 128 CTAs -> one wave
#define KC 32
#define NCH (DDIM / KC)          // 32 chunks per phase

#define GWST 1032                // bf16 elems/row (2064B; 8-row ldsm conflict-free)
#define WUST 56                  // bf16 elems/row (112B; 8-row ldsm conflict-free)
#define YS_STRIDE 52             // bf16
#define H2_STRIDE 52             // bf16

// ---- smem layout (bytes): no x staging ----
#define OFF_W   0
#define SZ_W    (DDIM * WUST * 2)                 // 114688 (gw uses 48*2064=99072)
#define OFF_Y   (OFF_W + SZ_W)                    // 26624
#define OFF_H2  (OFF_Y + MTILE * YS_STRIDE * 2)   // 26624
#define OFF_A48 (OFF_H2 + MTILE * H2_STRIDE * 2)  // 9216
#define OFF_SGW (OFF_A48 + RDIM * RDIM * 4)       // 192
#define OFF_CB  (OFF_SGW + RDIM * 4)              // 192
#define OFF_C48 (OFF_CB + RDIM * 4)               // 192
#define SMEM_TOTAL (OFF_C48 + RDIM * 4)           // 177728

// ---- global scratch (prep output) ----
__device__ __align__(16) __nv_bfloat16 g_gw[RDIM * DDIM];   // gamma (*) w_down
__device__ __align__(16) __nv_bfloat16 g_wu[DDIM * RDIM];
__device__ float g_sumgw[RDIM];
__device__ float g_cb[RDIM];
__device__ float g_c48[RDIM];
__device__ float g_A48T[RDIM * RDIM];

__device__ __forceinline__ float gelu_exact(float v) {
    return 0.5f * v * (1.0f + erff(v * 0.70710678118654752440f));
}

__device__ __forceinline__ void mma_bf16(float* c, unsigned a0, unsigned a1, unsigned a2,
                                         unsigned a3, unsigned b0, unsigned b1) {
    asm volatile(
        "mma.sync.aligned.m16n8k16.row.col.f32.bf16.bf16.f32 "
        "{%0,%1,%2,%3}, {%4,%5,%6,%7}, {%8,%9}, {%0,%1,%2,%3};\n"
        : "+f"(c[0]), "+f"(c[1]), "+f"(c[2]), "+f"(c[3])
        : "r"(a0), "r"(a1), "r"(a2), "r"(a3), "r"(b0), "r"(b1));
}

__device__ __forceinline__ void ldsm_x4(unsigned* r, unsigned addr) {
    asm volatile("ldmatrix.sync.aligned.m8n8.x4.shared.b16 {%0,%1,%2,%3}, [%4];"
                 : "=r"(r[0]), "=r"(r[1]), "=r"(r[2]), "=r"(r[3]) : "r"(addr));
}

__device__ __forceinline__ unsigned pack2(float a, float b) {
    __nv_bfloat162 p = __floats2bfloat162_rn(a, b);
    return *(unsigned*)&p;
}
__device__ __forceinline__ uint2 pack_bf16x4(float a, float b, float c, float d) {
    uint2 pk;
    pk.x = pack2(a, b);
    pk.y = pack2(c, d);
    return pk;
}

__device__ __forceinline__ void cp16(unsigned dst, const void* src) {
    asm volatile("cp.async.cg.shared.global [%0], [%1], 16;\n" :: "r"(dst), "l"(src));
}
__device__ __forceinline__ void cp_commit() {
    asm volatile("cp.async.commit_group;\n");
}
template <int N>
__device__ __forceinline__ void cp_wait() {
    asm volatile("cp.async.wait_group %0;\n" :: "n"(N));
}

// One butterfly round of the 4-lane pair transpose.
// s selects which half this lane contributes/replaces; dist is the xor distance.
__device__ __forceinline__ void xr(float2& lo, float2& hi, bool s, int dist) {
    float2 v;
    v.x = s ? lo.x : hi.x;
    v.y = s ? lo.y : hi.y;
    float2 w;
    w.x = __shfl_xor_sync(0xffffffffu, v.x, dist);
    w.y = __shfl_xor_sync(0xffffffffu, v.y, dist);
    if (s) lo = w; else hi = w;
}
// forward: natural pairs (2t4,2t4+1) -> frag pairs (t4, t4+4)
__device__ __forceinline__ void xpose_fwd(float2& lo, float2& hi, int t4) {
    xr(lo, hi, (t4 & 1) != 0, 1);
    xr(lo, hi, (t4 & 2) != 0, 2);
}
// inverse: frag pairs -> natural pairs
__device__ __forceinline__ void xpose_inv(float2& lo, float2& hi, int t4) {
    xr(lo, hi, (t4 & 2) != 0, 2);
    xr(lo, hi, (t4 & 1) != 0, 1);
}

// Natural-layout chunk loader: 4 x LDG.128, 8 rows x 64B per instr (32 wf/chunk).
// d[0]=row g cols t4*4.. , d[1]=row g+8 same, d[2]/d[3]: +16 cols.
__device__ __forceinline__ void load_chunk4(float4* d, const float* base, int g, int t4) {
    d[0] = *(const float4*)(base + (size_t)g * DDIM + t4 * 4);
    d[1] = *(const float4*)(base + (size_t)(g + 8) * DDIM + t4 * 4);
    d[2] = *(const float4*)(base + (size_t)g * DDIM + 16 + t4 * 4);
    d[3] = *(const float4*)(base + (size_t)(g + 8) * DDIM + 16 + t4 * 4);
}

// ============================================================================
// prep: gamma-folded w_down -> bf16, w_up -> bf16, sumgw/cb, collapsed 48x48.
// ============================================================================
__global__ void prep_kernel(const float* __restrict__ gamma, const float* __restrict__ beta,
                            const float* __restrict__ w_down, const float* __restrict__ w_to_mv,
                            const float* __restrict__ w_equi, const float* __restrict__ b_equi,
                            const float* __restrict__ w_from_mv, const float* __restrict__ w_up) {
    int tid = threadIdx.x, lane = tid & 31;
    int gtid = blockIdx.x * blockDim.x + tid;
    int nth = gridDim.x * blockDim.x;
    int gwarp = gtid >> 5;

    if (gwarp < RDIM) {
        int r = gwarp;
        float s = 0.f, cb = 0.f;
        #pragma unroll
        for (int it = 0; it < 8; it++) {
            int d = it * 128 + lane * 4;
            float4 w  = *(const float4*)(w_down + (size_t)r * DDIM + d);
            float4 gv = *(const float4*)(gamma + d);
            float4 bv = *(const float4*)(beta + d);
            uint2 pk = pack_bf16x4(w.x * gv.x, w.y * gv.y, w.z * gv.z, w.w * gv.w);
            *(uint2*)(g_gw + (size_t)r * DDIM + d) = pk;
            __nv_bfloat162 b0 = *(__nv_bfloat162*)&pk.x;
            __nv_bfloat162 b1 = *(__nv_bfloat162*)&pk.y;
            s += __bfloat162float(b0.x) + __bfloat162float(b0.y)
               + __bfloat162float(b1.x) + __bfloat162float(b1.y);
            cb += w.x * bv.x + w.y * bv.y + w.z * bv.z + w.w * bv.w;
        }
        #pragma unroll
        for (int off = 16; off; off >>= 1) {
            s  += __shfl_xor_sync(0xffffffffu, s, off);
            cb += __shfl_xor_sync(0xffffffffu, cb, off);
        }
        if (lane == 0) { g_sumgw[r] = s; g_cb[r] = cb; }
    }
    for (int i = gtid; i < DDIM * RDIM / 4; i += nth) {
        float4 v = ((const float4*)w_up)[i];
        ((uint2*)g_wu)[i] = pack_bf16x4(v.x, v.y, v.z, v.w);
    }
    for (int i = gtid; i < RDIM * RDIM; i += nth) {
        int rp = i / RDIM, r = i - rp * RDIM;
        float a = 0.f;
        #pragma unroll
        for (int m = 0; m < 16; m++) {
            int gidx = (m == 0) ? 0 : (m < 5) ? 1 : (m < 11) ? 2 : (m < 15) ? 3 : 4;
            a += __ldg(w_from_mv + r * 16 + m) * __ldg(w_equi + gidx)
               * __ldg(w_to_mv + m * RDIM + rp);
        }
        g_A48T[i] = a;
    }
    for (int i = gtid; i < RDIM; i += nth)
        g_c48[i] = __ldg(w_from_mv + i * 16) * __ldg(b_equi);
}

// ============================================================================
// Fused kernel: natural float4 LDG/STG + register butterfly to/from frag
// layout. No x smem staging, no mainloop barriers, resident bf16 weights.
// ============================================================================
__global__ void __launch_bounds__(THREADS, 1) fused_kernel(
    const float* __restrict__ x, const float* __restrict__ scale_p,
    float* __restrict__ out)
{
    extern __shared__ char smem[];
    const unsigned sbase = (unsigned)__cvta_generic_to_shared(smem);
    __nv_bfloat16* y_s  = (__nv_bfloat16*)(smem + OFF_Y);
    __nv_bfloat16* h2_s = (__nv_bfloat16*)(smem + OFF_H2);
    float* A48T_s  = (float*)(smem + OFF_A48);
    float* sumgw_s = (float*)(smem + OFF_SGW);
    float* cb_s    = (float*)(smem + OFF_CB);
    float* c48_s   = (float*)(smem + OFF_C48);

    const int tid = threadIdx.x, lane = tid & 31, warp = tid >> 5;
    const int g = lane >> 2, t4 = lane & 3, t2 = t4 * 2;
    const int tok0 = blockIdx.x * MTILE;
    const int mrow = warp * 16;

    // LDSM lane mapping
    const int bn = ((lane >> 4) << 3) + (lane & 7);
    const int kh = (lane >> 3) & 1;

    const float* xwarp = x + (size_t)(tok0 + mrow) * DDIM;

    // ---- issue resident-gw cp.async burst ----
    for (int i = tid; i < RDIM * 128; i += THREADS) {
        int r = i >> 7, s = i & 127;
        cp16(sbase + OFF_W + r * (GWST * 2) + s * 16,
             (const char*)g_gw + (size_t)r * 2048 + s * 16);
    }
    cp_commit();

    // ---- preload x chunks 0,1 (natural float4 layout) ----
    float4 st[2][4];
    load_chunk4(st[0], xwarp, g, t4);
    load_chunk4(st[1], xwarp + KC, g, t4);

    // ---- small precomputed arrays ----
    for (int i = tid; i < RDIM * RDIM; i += THREADS) A48T_s[i] = g_A48T[i];
    for (int i = tid; i < RDIM; i += THREADS) {
        sumgw_s[i] = g_sumgw[i]; cb_s[i] = g_cb[i]; c48_s[i] = g_c48[i];
    }
    float scale = __ldg(scale_p);

    cp_wait<0>();
    __syncthreads();   // gw resident + arrays visible

    // ---- phase A mainloop: per-warp, zero barriers ----
    float acc[6][4];
    #pragma unroll
    for (int j = 0; j < 6; j++)
        #pragma unroll
        for (int q = 0; q < 4; q++) acc[j][q] = 0.f;
    float ps0 = 0.f, pss0 = 0.f, ps1 = 0.f, pss1 = 0.f;

    const unsigned gwb = sbase + OFF_W + bn * (GWST * 2) + kh * 16;

    #pragma unroll 2
    for (int kc = 0; kc < NCH; kc++) {
        float4 v[4];
        #pragma unroll
        for (int i = 0; i < 4; i++) v[i] = st[kc & 1][i];
        if (kc + 2 < NCH)
            load_chunk4(st[kc & 1], xwarp + (kc + 2) * KC, g, t4);

        // stats on raw float4s (same value set per quad as frag layout)
        ps0  += (v[0].x + v[0].y) + (v[0].z + v[0].w) + (v[2].x + v[2].y) + (v[2].z + v[2].w);
        pss0 += (v[0].x * v[0].x + v[0].y * v[0].y) + (v[0].z * v[0].z + v[0].w * v[0].w)
              + (v[2].x * v[2].x + v[2].y * v[2].y) + (v[2].z * v[2].z + v[2].w * v[2].w);
        ps1  += (v[1].x + v[1].y) + (v[1].z + v[1].w) + (v[3].x + v[3].y) + (v[3].z + v[3].w);
        pss1 += (v[1].x * v[1].x + v[1].y * v[1].y) + (v[1].z * v[1].z + v[1].w * v[1].w)
              + (v[3].x * v[3].x + v[3].y * v[3].y) + (v[3].z * v[3].z + v[3].w * v[3].w);

        #pragma unroll
        for (int kk = 0; kk < 2; kk++) {
            float2 lo0 = make_float2(v[kk * 2].x, v[kk * 2].y);
            float2 hi0 = make_float2(v[kk * 2].z, v[kk * 2].w);
            float2 lo1 = make_float2(v[kk * 2 + 1].x, v[kk * 2 + 1].y);
            float2 hi1 = make_float2(v[kk * 2 + 1].z, v[kk * 2 + 1].w);
            xpose_fwd(lo0, hi0, t4);
            xpose_fwd(lo1, hi1, t4);
            unsigned a0 = pack2(lo0.x, lo0.y);
            unsigned a1 = pack2(lo1.x, lo1.y);
            unsigned a2 = pack2(hi0.x, hi0.y);
            unsigned a3 = pack2(hi1.x, hi1.y);

            unsigned br[3][4];
            #pragma unroll
            for (int p = 0; p < 3; p++)
                ldsm_x4(br[p], gwb + p * 16 * (GWST * 2) + kc * 64 + kk * 32);
            #pragma unroll
            for (int j = 0; j < 6; j++)
                mma_bf16(acc[j], a0, a1, a2, a3,
                         br[j >> 1][(j & 1) * 2], br[j >> 1][(j & 1) * 2 + 1]);
        }
    }

    // ---- stats: reduce over t4 lanes; LN params in registers ----
    #pragma unroll
    for (int off = 1; off <= 2; off <<= 1) {
        ps0  += __shfl_xor_sync(0xffffffffu, ps0, off);
        pss0 += __shfl_xor_sync(0xffffffffu, pss0, off);
        ps1  += __shfl_xor_sync(0xffffffffu, ps1, off);
        pss1 += __shfl_xor_sync(0xffffffffu, pss1, off);
    }
    float mu0 = ps0 * (1.0f / DDIM);
    float ri0 = rsqrtf(pss0 * (1.0f / DDIM) - mu0 * mu0 + 1e-5f);
    float mu1 = ps1 * (1.0f / DDIM);
    float ri1 = rsqrtf(pss1 * (1.0f / DDIM) - mu1 * mu1 + 1e-5f);

    __syncthreads();   // all gw reads done -> safe to overwrite W region

    // ---- issue resident-wu cp.async burst (overlaps the mid-section) ----
    for (int i = tid; i < DDIM * 6; i += THREADS) {
        int d = i / 6, s = i - d * 6;
        cp16(sbase + OFF_W + d * (WUST * 2) + s * 16,
             (const char*)g_wu + (size_t)d * 96 + s * 16);
    }
    cp_commit();

    // ---- y = gelu(rinv*(acc - mu*sumgw) + cb) -> bf16 ----
    {
        int r0 = mrow + g, r1 = r0 + 8;
        #pragma unroll
        for (int j = 0; j < 6; j++) {
            int c0 = j * 8 + t2, c1 = c0 + 1;
            float y00 = gelu_exact(ri0 * (acc[j][0] - mu0 * sumgw_s[c0]) + cb_s[c0]);
            float y01 = gelu_exact(ri0 * (acc[j][1] - mu0 * sumgw_s[c1]) + cb_s[c1]);
            float y10 = gelu_exact(ri1 * (acc[j][2] - mu1 * sumgw_s[c0]) + cb_s[c0]);
            float y11 = gelu_exact(ri1 * (acc[j][3] - mu1 * sumgw_s[c1]) + cb_s[c1]);
            *(__nv_bfloat162*)(y_s + r0 * YS_STRIDE + c0) = __floats2bfloat162_rn(y00, y01);
            *(__nv_bfloat162*)(y_s + r1 * YS_STRIDE + c0) = __floats2bfloat162_rn(y10, y11);
        }
    }

    // ---- prefetch phase-C x chunks 0,1 (natural layout, covered by middle) ----
    load_chunk4(st[0], xwarp, g, t4);
    load_chunk4(st[1], xwarp + KC, g, t4);

    __syncthreads();   // y visible

    // ---- middle: h2 = gelu(A48 @ y + c48) -> bf16 ----
    {
        int t = tid >> 1;
        int rbase = (tid & 1) * 24;
        const __nv_bfloat16* yrow = y_s + t * YS_STRIDE;
        float h2v[24];
        #pragma unroll
        for (int r = 0; r < 24; r++) h2v[r] = c48_s[rbase + r];
        #pragma unroll 4
        for (int kp2 = 0; kp2 < RDIM / 2; kp2++) {
            __nv_bfloat162 yp = *(const __nv_bfloat162*)(yrow + kp2 * 2);
            float yv0 = __bfloat162float(yp.x), yv1 = __bfloat162float(yp.y);
            const float* a0 = A48T_s + (kp2 * 2) * RDIM + rbase;
            const float* a1 = a0 + RDIM;
            #pragma unroll
            for (int r = 0; r < 24; r++) h2v[r] += yv0 * a0[r] + yv1 * a1[r];
        }
        __nv_bfloat16* op = h2_s + t * H2_STRIDE + rbase;
        #pragma unroll
        for (int r = 0; r < 24; r += 2) {
            __nv_bfloat162 p = __floats2bfloat162_rn(gelu_exact(h2v[r]), gelu_exact(h2v[r + 1]));
            *(__nv_bfloat162*)(op + r) = p;
        }
    }
    cp_wait<0>();      // wu landed
    __syncthreads();   // h2 + wu visible

    // ---- phase C: out = x + scale*(h2 @ wu^T); natural-layout I/O ----
    unsigned afr[3][4];
    #pragma unroll
    for (int kk = 0; kk < 3; kk++) {
        afr[kk][0] = *(const unsigned*)(h2_s + (mrow + g) * H2_STRIDE + kk * 16 + t2);
        afr[kk][1] = *(const unsigned*)(h2_s + (mrow + g + 8) * H2_STRIDE + kk * 16 + t2);
        afr[kk][2] = *(const unsigned*)(h2_s + (mrow + g) * H2_STRIDE + kk * 16 + 8 + t2);
        afr[kk][3] = *(const unsigned*)(h2_s + (mrow + g + 8) * H2_STRIDE + kk * 16 + 8 + t2);
    }

    #pragma unroll 2
    for (int nc = 0; nc < NCH; nc++) {
        float4 xv[4];
        #pragma unroll
        for (int i = 0; i < 4; i++) xv[i] = st[nc & 1][i];
        if (nc + 2 < NCH)
            load_chunk4(st[nc & 1], xwarp + (nc + 2) * KC, g, t4);

        unsigned wub = sbase + OFF_W + (nc * 32 + bn) * (WUST * 2) + kh * 16;
        float uacc[4][4];
        #pragma unroll
        for (int j = 0; j < 4; j++)
            #pragma unroll
            for (int q = 0; q < 4; q++) uacc[j][q] = 0.f;

        #pragma unroll
        for (int kk = 0; kk < 3; kk++) {
            unsigned br[2][4];
            ldsm_x4(br[0], wub + kk * 32);
            ldsm_x4(br[1], wub + 16 * (WUST * 2) + kk * 32);
            #pragma unroll
            for (int j = 0; j < 4; j++)
                mma_bf16(uacc[j], afr[kk][0], afr[kk][1], afr[kk][2], afr[kk][3],
                         br[j >> 1][(j & 1) * 2], br[j >> 1][(j & 1) * 2 + 1]);
        }

        size_t row0 = (size_t)(tok0 + mrow + g) * DDIM + nc * KC;
        size_t row1 = row0 + 8 * (size_t)DDIM;
        // inverse-transpose uacc (frag -> natural pairs), fuse residual, STG.128
        #pragma unroll
        for (int grp = 0; grp < 2; grp++) {
            // row g
            float2 lo0 = make_float2(uacc[grp * 2][0], uacc[grp * 2][1]);
            float2 hi0 = make_float2(uacc[grp * 2 + 1][0], uacc[grp * 2 + 1][1]);
            xpose_inv(lo0, hi0, t4);
            float4 xr0 = xv[grp * 2];
            float4 o0 = make_float4(xr0.x + scale * lo0.x, xr0.y + scale * lo0.y,
                                    xr0.z + scale * hi0.x, xr0.w + scale * hi0.y);
            __stcs((float4*)(out + row0 + grp * 16 + t4 * 4), o0);
            // row g+8
            float2 lo1 = make_float2(uacc[grp * 2][2], uacc[grp * 2][3]);
            float2 hi1 = make_float2(uacc[grp * 2 + 1][2], uacc[grp * 2 + 1][3]);
            xpose_inv(lo1, hi1, t4);
            float4 xr1 = xv[grp * 2 + 1];
            float4 o1 = make_float4(xr1.x + scale * lo1.x, xr1.y + scale * lo1.y,
                                    xr1.z + scale * hi1.x, xr1.w + scale * hi1.y);
            __stcs((float4*)(out + row1 + grp * 16 + t4 * 4), o1);
        }
    }
}

extern "C" void kernel_launch(void* const* d_in, const int* in_sizes, int n_in,
                              void* d_out, int out_size) {
    const float* x         = (const float*)d_in[0];
    const float* gamma     = (const float*)d_in[1];
    const float* beta      = (const float*)d_in[2];
    const float* w_down    = (const float*)d_in[3];
    const float* w_to_mv   = (const float*)d_in[4];
    const float* w_equi    = (const float*)d_in[5];
    const float* b_equi    = (const float*)d_in[6];
    const float* w_from_mv = (const float*)d_in[7];
    const float* w_up      = (const float*)d_in[8];
    const float* scale     = (const float*)d_in[9];
    float* out = (float*)d_out;

    cudaFuncSetAttribute(fused_kernel, cudaFuncAttributeMaxDynamicSharedMemorySize, SMEM_TOTAL);
    prep_kernel<<<128, 256>>>(gamma, beta, w_down, w_to_mv, w_equi, b_equi, w_from_mv, w_up);
    fused_kernel<<<NCTAS, THREADS, SMEM_TOTAL>>>(x, scale, out);
}